// round 1
// baseline (speedup 1.0000x reference)
#include <cuda_runtime.h>
#include <math.h>

constexpr int LAY = 2;     // layers
constexpr int BS  = 32;    // batch
constexpr int TS  = 256;   // time
constexpr int NS  = 1024;  // input features
constexpr int MS  = 1024;  // hidden
constexpr int JS  = 4096;  // 4*MS gate dim

// ---- scratch (static device globals; no allocation at runtime) ----
__device__ float g_G[(size_t)TS * BS * JS];     // precomputed input gates, time-major rows (t*BS+b, j)
__device__ float g_hbuf[(size_t)TS * BS * MS];  // layer-0 outputs, time-major (input rows for layer-1 GEMM)
__device__ float g_hping[BS * MS];              // recurrent h state ping
__device__ float g_hpong[BS * MS];              // recurrent h state pong

// ------------------------------------------------------------------
__global__ void init_c_kernel(const float* __restrict__ c, float* __restrict__ out_c) {
    int i = blockIdx.x * blockDim.x + threadIdx.x;
    if (i < LAY * BS * MS) out_c[i] = c[i];
}

__global__ void init_h_kernel(const float* __restrict__ h_l) {
    int i = blockIdx.x * blockDim.x + threadIdx.x;
    if (i < BS * MS) g_hping[i] = h_l[i];
}

// ------------------------------------------------------------------
// G[r][j] = sum_k inp_row_r[k] * Wih[j][k] + bih[j] + bhh[j]
// r = t*BS + b. Layer 0 input rows come from x (B,T,N); layer 1 from g_hbuf (time-major).
// Tile: 64 rows x 64 cols, BK=16, 256 threads, 4x4 micro-tile.
__global__ __launch_bounds__(256)
void gemm_input_kernel(const float* __restrict__ x,
                       const float* __restrict__ Wih_l,
                       const float* __restrict__ bih_l,
                       const float* __restrict__ bhh_l,
                       int layer)
{
    __shared__ float As[16][68];   // [k][row], padded stride 68 (16B-aligned rows, conflict-free)
    __shared__ float Bs[16][68];   // [k][col]

    int tid  = threadIdx.x;
    int row0 = blockIdx.y * 64;
    int col0 = blockIdx.x * 64;

    int lrow = tid >> 2;          // 0..63
    int lk   = (tid & 3) * 4;     // 0,4,8,12

    int r = row0 + lrow;
    const float* Aptr;
    if (layer == 0) {
        int tt = r >> 5;          // r / BS
        int bb = r & 31;          // r % BS
        Aptr = x + ((size_t)bb * TS + tt) * NS;
    } else {
        Aptr = g_hbuf + (size_t)r * MS;
    }
    const float* Bptr = Wih_l + (size_t)(col0 + lrow) * 1024;

    int ty = tid >> 4;            // 0..15 (row group)
    int tx = tid & 15;            // 0..15 (col group)

    float acc[4][4];
    #pragma unroll
    for (int i = 0; i < 4; i++)
        #pragma unroll
        for (int j = 0; j < 4; j++) acc[i][j] = 0.f;

    for (int k0 = 0; k0 < 1024; k0 += 16) {
        float4 av = *(const float4*)(Aptr + k0 + lk);
        float4 bv = *(const float4*)(Bptr + k0 + lk);
        __syncthreads();
        As[lk + 0][lrow] = av.x; As[lk + 1][lrow] = av.y;
        As[lk + 2][lrow] = av.z; As[lk + 3][lrow] = av.w;
        Bs[lk + 0][lrow] = bv.x; Bs[lk + 1][lrow] = bv.y;
        Bs[lk + 2][lrow] = bv.z; Bs[lk + 3][lrow] = bv.w;
        __syncthreads();
        #pragma unroll
        for (int k = 0; k < 16; k++) {
            float4 a4 = *(const float4*)&As[k][ty * 4];
            float4 b4 = *(const float4*)&Bs[k][tx * 4];
            acc[0][0] += a4.x * b4.x; acc[0][1] += a4.x * b4.y;
            acc[0][2] += a4.x * b4.z; acc[0][3] += a4.x * b4.w;
            acc[1][0] += a4.y * b4.x; acc[1][1] += a4.y * b4.y;
            acc[1][2] += a4.y * b4.z; acc[1][3] += a4.y * b4.w;
            acc[2][0] += a4.z * b4.x; acc[2][1] += a4.z * b4.y;
            acc[2][2] += a4.z * b4.z; acc[2][3] += a4.z * b4.w;
            acc[3][0] += a4.w * b4.x; acc[3][1] += a4.w * b4.y;
            acc[3][2] += a4.w * b4.z; acc[3][3] += a4.w * b4.w;
        }
    }

    int cbase = col0 + tx * 4;
    float b0 = bih_l[cbase + 0] + bhh_l[cbase + 0];
    float b1 = bih_l[cbase + 1] + bhh_l[cbase + 1];
    float b2 = bih_l[cbase + 2] + bhh_l[cbase + 2];
    float b3 = bih_l[cbase + 3] + bhh_l[cbase + 3];
    #pragma unroll
    for (int i = 0; i < 4; i++) {
        int row = row0 + ty * 4 + i;
        float4 o;
        o.x = acc[i][0] + b0;
        o.y = acc[i][1] + b1;
        o.z = acc[i][2] + b2;
        o.w = acc[i][3] + b3;
        *(float4*)&g_G[(size_t)row * JS + cbase] = o;
    }
}

// ------------------------------------------------------------------
// One LSTM timestep for one layer, fully fused:
//   gates = G[t] + h_in @ Whh^T   (tile: 8 m-units x 4 gates x 32 batch per CTA)
//   c,h update; emit h to hbuf (layer 0) or outs (layer 1).
// Grid: 128 CTAs (m tiles of 8), 128 threads.
__global__ __launch_bounds__(128)
void rec_step_kernel(const float* __restrict__ Whh_l,
                     float* __restrict__ cstate,   // out_c + l*BS*MS, updated in place
                     float* __restrict__ hfinal,   // out_h + l*BS*MS, written at t==TS-1
                     float* __restrict__ outs,     // d_out base (B,T,M)
                     int t, int layer)
{
    __shared__ float w_s[32][36];     // [k][jrow]   jrow = gate*8 + mloc
    __shared__ float h_s[32][36];     // [k][b]
    __shared__ float gate_s[32][33];  // [jrow][b]

    const float* hin = (t & 1) ? g_hpong : g_hping;
    float*       hout = (t & 1) ? g_hping : g_hpong;

    int tid    = threadIdx.x;
    int m_base = blockIdx.x * 8;

    // loading roles
    int jrow = tid >> 2;     // 0..31
    int kq   = tid & 3;      // 0..3
    int gidx  = jrow >> 3;   // gate
    int mloc0 = jrow & 7;
    const float* wp = Whh_l + ((size_t)gidx * MS + m_base + mloc0) * 1024;
    const float* hp = hin + (size_t)jrow * 1024;   // jrow doubles as batch row for h loads

    // compute roles
    int tb = tid & 15;       // 0..15 -> 2 batches each
    int tj = tid >> 4;       // 0..7  -> 4 jrows each

    float acc[4][2];
    #pragma unroll
    for (int i = 0; i < 4; i++) { acc[i][0] = 0.f; acc[i][1] = 0.f; }

    for (int k0 = 0; k0 < 1024; k0 += 32) {
        float4 w1 = *(const float4*)(wp + k0 + kq * 4);
        float4 w2 = *(const float4*)(wp + k0 + 16 + kq * 4);
        float4 h1 = *(const float4*)(hp + k0 + kq * 4);
        float4 h2 = *(const float4*)(hp + k0 + 16 + kq * 4);
        __syncthreads();
        w_s[kq * 4 + 0][jrow] = w1.x;  w_s[kq * 4 + 1][jrow] = w1.y;
        w_s[kq * 4 + 2][jrow] = w1.z;  w_s[kq * 4 + 3][jrow] = w1.w;
        w_s[kq * 4 + 16][jrow] = w2.x; w_s[kq * 4 + 17][jrow] = w2.y;
        w_s[kq * 4 + 18][jrow] = w2.z; w_s[kq * 4 + 19][jrow] = w2.w;
        h_s[kq * 4 + 0][jrow] = h1.x;  h_s[kq * 4 + 1][jrow] = h1.y;
        h_s[kq * 4 + 2][jrow] = h1.z;  h_s[kq * 4 + 3][jrow] = h1.w;
        h_s[kq * 4 + 16][jrow] = h2.x; h_s[kq * 4 + 17][jrow] = h2.y;
        h_s[kq * 4 + 18][jrow] = h2.z; h_s[kq * 4 + 19][jrow] = h2.w;
        __syncthreads();
        #pragma unroll
        for (int kk = 0; kk < 32; kk++) {
            float4 wv = *(const float4*)&w_s[kk][tj * 4];
            float2 hv = *(const float2*)&h_s[kk][tb * 2];
            acc[0][0] += wv.x * hv.x; acc[0][1] += wv.x * hv.y;
            acc[1][0] += wv.y * hv.x; acc[1][1] += wv.y * hv.y;
            acc[2][0] += wv.z * hv.x; acc[2][1] += wv.z * hv.y;
            acc[3][0] += wv.w * hv.x; acc[3][1] += wv.w * hv.y;
        }
    }

    // add precomputed input-gate contribution, stage to smem for activation
    #pragma unroll
    for (int i = 0; i < 4; i++) {
        int jr = tj * 4 + i;
        int jg = (jr >> 3) * MS + m_base + (jr & 7);
        const float* gp = &g_G[((size_t)t * BS) * JS + jg];
        #pragma unroll
        for (int b2 = 0; b2 < 2; b2++) {
            int b = tb * 2 + b2;
            gate_s[jr][b] = acc[i][b2] + gp[(size_t)b * JS];
        }
    }
    __syncthreads();

    // activation + cell update: 256 cells (8 m x 32 b), 2 per thread
    #pragma unroll
    for (int c2 = 0; c2 < 2; c2++) {
        int cell = tid * 2 + c2;
        int ml = cell >> 5;
        int b  = cell & 31;
        float ig = gate_s[ml][b];
        float fg = gate_s[8 + ml][b];
        float gg = gate_s[16 + ml][b];
        float og = gate_s[24 + ml][b];
        ig = 1.f / (1.f + expf(-ig));
        fg = 1.f / (1.f + expf(-fg));
        og = 1.f / (1.f + expf(-og));
        gg = tanhf(gg);
        int mg = m_base + ml;
        size_t ci = (size_t)b * MS + mg;
        float cn = fg * cstate[ci] + ig * gg;
        float hn = og * tanhf(cn);
        cstate[ci] = cn;
        hout[ci] = hn;
        if (t == TS - 1) hfinal[ci] = hn;
        if (layer == 0) g_hbuf[((size_t)t * BS + b) * MS + mg] = hn;
        else            outs[((size_t)b * TS + t) * MS + mg] = hn;
    }
}

// ------------------------------------------------------------------
extern "C" void kernel_launch(void* const* d_in, const int* in_sizes, int n_in,
                              void* d_out, int out_size)
{
    const float* x   = (const float*)d_in[0];
    const float* h   = (const float*)d_in[1];
    const float* c   = (const float*)d_in[2];
    const float* Wih = (const float*)d_in[3];
    const float* Whh = (const float*)d_in[4];
    const float* bih = (const float*)d_in[5];
    const float* bhh = (const float*)d_in[6];

    float* outs  = (float*)d_out;                       // (B,T,M)
    float* out_h = outs + (size_t)BS * TS * MS;         // (L,B,M)
    float* out_c = out_h + (size_t)LAY * BS * MS;       // (L,B,M)

    init_c_kernel<<<(LAY * BS * MS + 255) / 256, 256>>>(c, out_c);

    for (int l = 0; l < LAY; l++) {
        gemm_input_kernel<<<dim3(JS / 64, (TS * BS) / 64), 256>>>(
            x, Wih + (size_t)l * JS * 1024, bih + (size_t)l * JS, bhh + (size_t)l * JS, l);
        init_h_kernel<<<(BS * MS + 255) / 256, 256>>>(h + (size_t)l * BS * MS);
        for (int t = 0; t < TS; t++) {
            rec_step_kernel<<<MS / 8, 128>>>(
                Whh + (size_t)l * JS * 1024,
                out_c + (size_t)l * BS * MS,
                out_h + (size_t)l * BS * MS,
                outs, t, l);
        }
    }
}

// round 2
// speedup vs baseline: 1.0008x; 1.0008x over previous
#include <cuda_runtime.h>
#include <math.h>

constexpr int LAY = 2;     // layers
constexpr int BS  = 32;    // batch
constexpr int TS  = 256;   // time
constexpr int NS  = 1024;  // input features
constexpr int MS  = 1024;  // hidden
constexpr int JS  = 4096;  // 4*MS gate dim

// ---- scratch (static device globals; no allocation at runtime) ----
__device__ float g_G[(size_t)TS * BS * JS];     // precomputed input gates, time-major rows (t*BS+b, j)
__device__ float g_hbuf[(size_t)TS * BS * MS];  // layer-0 outputs, time-major (input rows for layer-1 GEMM)
__device__ float g_hping[BS * MS];              // recurrent h state ping
__device__ float g_hpong[BS * MS];              // recurrent h state pong

// ------------------------------------------------------------------
__global__ void init_c_kernel(const float* __restrict__ c, float* __restrict__ out_c) {
    int i = blockIdx.x * blockDim.x + threadIdx.x;
    if (i < LAY * BS * MS) out_c[i] = c[i];
}

__global__ void init_h_kernel(const float* __restrict__ h_l) {
    int i = blockIdx.x * blockDim.x + threadIdx.x;
    if (i < BS * MS) g_hping[i] = h_l[i];
}

// ------------------------------------------------------------------
// G[r][j] = sum_k inp_row_r[k] * Wih[j][k] + bih[j] + bhh[j]
// r = t*BS + b. Layer 0 input rows come from x (B,T,N); layer 1 from g_hbuf (time-major).
// Tile: 64 rows x 64 cols, BK=16, 256 threads, 4x4 micro-tile.
__global__ __launch_bounds__(256)
void gemm_input_kernel(const float* __restrict__ x,
                       const float* __restrict__ Wih_l,
                       const float* __restrict__ bih_l,
                       const float* __restrict__ bhh_l,
                       int layer)
{
    __shared__ float As[16][68];   // [k][row], padded stride 68 (16B-aligned rows, conflict-free)
    __shared__ float Bs[16][68];   // [k][col]

    int tid  = threadIdx.x;
    int row0 = blockIdx.y * 64;
    int col0 = blockIdx.x * 64;

    int lrow = tid >> 2;          // 0..63
    int lk   = (tid & 3) * 4;     // 0,4,8,12

    int r = row0 + lrow;
    const float* Aptr;
    if (layer == 0) {
        int tt = r >> 5;          // r / BS
        int bb = r & 31;          // r % BS
        Aptr = x + ((size_t)bb * TS + tt) * NS;
    } else {
        Aptr = g_hbuf + (size_t)r * MS;
    }
    const float* Bptr = Wih_l + (size_t)(col0 + lrow) * 1024;

    int ty = tid >> 4;            // 0..15 (row group)
    int tx = tid & 15;            // 0..15 (col group)

    float acc[4][4];
    #pragma unroll
    for (int i = 0; i < 4; i++)
        #pragma unroll
        for (int j = 0; j < 4; j++) acc[i][j] = 0.f;

    for (int k0 = 0; k0 < 1024; k0 += 16) {
        float4 av = *(const float4*)(Aptr + k0 + lk);
        float4 bv = *(const float4*)(Bptr + k0 + lk);
        __syncthreads();
        As[lk + 0][lrow] = av.x; As[lk + 1][lrow] = av.y;
        As[lk + 2][lrow] = av.z; As[lk + 3][lrow] = av.w;
        Bs[lk + 0][lrow] = bv.x; Bs[lk + 1][lrow] = bv.y;
        Bs[lk + 2][lrow] = bv.z; Bs[lk + 3][lrow] = bv.w;
        __syncthreads();
        #pragma unroll
        for (int k = 0; k < 16; k++) {
            float4 a4 = *(const float4*)&As[k][ty * 4];
            float4 b4 = *(const float4*)&Bs[k][tx * 4];
            acc[0][0] += a4.x * b4.x; acc[0][1] += a4.x * b4.y;
            acc[0][2] += a4.x * b4.z; acc[0][3] += a4.x * b4.w;
            acc[1][0] += a4.y * b4.x; acc[1][1] += a4.y * b4.y;
            acc[1][2] += a4.y * b4.z; acc[1][3] += a4.y * b4.w;
            acc[2][0] += a4.z * b4.x; acc[2][1] += a4.z * b4.y;
            acc[2][2] += a4.z * b4.z; acc[2][3] += a4.z * b4.w;
            acc[3][0] += a4.w * b4.x; acc[3][1] += a4.w * b4.y;
            acc[3][2] += a4.w * b4.z; acc[3][3] += a4.w * b4.w;
        }
    }

    int cbase = col0 + tx * 4;
    float b0 = bih_l[cbase + 0] + bhh_l[cbase + 0];
    float b1 = bih_l[cbase + 1] + bhh_l[cbase + 1];
    float b2 = bih_l[cbase + 2] + bhh_l[cbase + 2];
    float b3 = bih_l[cbase + 3] + bhh_l[cbase + 3];
    #pragma unroll
    for (int i = 0; i < 4; i++) {
        int row = row0 + ty * 4 + i;
        float4 o;
        o.x = acc[i][0] + b0;
        o.y = acc[i][1] + b1;
        o.z = acc[i][2] + b2;
        o.w = acc[i][3] + b3;
        *(float4*)&g_G[(size_t)row * JS + cbase] = o;
    }
}

// ------------------------------------------------------------------
// One LSTM timestep for one layer, fully fused:
//   gates = G[t] + h_in @ Whh^T   (tile: 8 m-units x 4 gates x 32 batch per CTA)
//   c,h update; emit h to hbuf (layer 0) or outs (layer 1).
// Grid: 128 CTAs (m tiles of 8), 128 threads.
__global__ __launch_bounds__(128)
void rec_step_kernel(const float* __restrict__ Whh_l,
                     float* __restrict__ cstate,   // out_c + l*BS*MS, updated in place
                     float* __restrict__ hfinal,   // out_h + l*BS*MS, written at t==TS-1
                     float* __restrict__ outs,     // d_out base (B,T,M)
                     int t, int layer)
{
    __shared__ float w_s[32][36];     // [k][jrow]   jrow = gate*8 + mloc
    __shared__ float h_s[32][36];     // [k][b]
    __shared__ float gate_s[32][33];  // [jrow][b]

    const float* hin = (t & 1) ? g_hpong : g_hping;
    float*       hout = (t & 1) ? g_hping : g_hpong;

    int tid    = threadIdx.x;
    int m_base = blockIdx.x * 8;

    // loading roles
    int jrow = tid >> 2;     // 0..31
    int kq   = tid & 3;      // 0..3
    int gidx  = jrow >> 3;   // gate
    int mloc0 = jrow & 7;
    const float* wp = Whh_l + ((size_t)gidx * MS + m_base + mloc0) * 1024;
    const float* hp = hin + (size_t)jrow * 1024;   // jrow doubles as batch row for h loads

    // compute roles
    int tb = tid & 15;       // 0..15 -> 2 batches each
    int tj = tid >> 4;       // 0..7  -> 4 jrows each

    float acc[4][2];
    #pragma unroll
    for (int i = 0; i < 4; i++) { acc[i][0] = 0.f; acc[i][1] = 0.f; }

    for (int k0 = 0; k0 < 1024; k0 += 32) {
        float4 w1 = *(const float4*)(wp + k0 + kq * 4);
        float4 w2 = *(const float4*)(wp + k0 + 16 + kq * 4);
        float4 h1 = *(const float4*)(hp + k0 + kq * 4);
        float4 h2 = *(const float4*)(hp + k0 + 16 + kq * 4);
        __syncthreads();
        w_s[kq * 4 + 0][jrow] = w1.x;  w_s[kq * 4 + 1][jrow] = w1.y;
        w_s[kq * 4 + 2][jrow] = w1.z;  w_s[kq * 4 + 3][jrow] = w1.w;
        w_s[kq * 4 + 16][jrow] = w2.x; w_s[kq * 4 + 17][jrow] = w2.y;
        w_s[kq * 4 + 18][jrow] = w2.z; w_s[kq * 4 + 19][jrow] = w2.w;
        h_s[kq * 4 + 0][jrow] = h1.x;  h_s[kq * 4 + 1][jrow] = h1.y;
        h_s[kq * 4 + 2][jrow] = h1.z;  h_s[kq * 4 + 3][jrow] = h1.w;
        h_s[kq * 4 + 16][jrow] = h2.x; h_s[kq * 4 + 17][jrow] = h2.y;
        h_s[kq * 4 + 18][jrow] = h2.z; h_s[kq * 4 + 19][jrow] = h2.w;
        __syncthreads();
        #pragma unroll
        for (int kk = 0; kk < 32; kk++) {
            float4 wv = *(const float4*)&w_s[kk][tj * 4];
            float2 hv = *(const float2*)&h_s[kk][tb * 2];
            acc[0][0] += wv.x * hv.x; acc[0][1] += wv.x * hv.y;
            acc[1][0] += wv.y * hv.x; acc[1][1] += wv.y * hv.y;
            acc[2][0] += wv.z * hv.x; acc[2][1] += wv.z * hv.y;
            acc[3][0] += wv.w * hv.x; acc[3][1] += wv.w * hv.y;
        }
    }

    // add precomputed input-gate contribution, stage to smem for activation
    #pragma unroll
    for (int i = 0; i < 4; i++) {
        int jr = tj * 4 + i;
        int jg = (jr >> 3) * MS + m_base + (jr & 7);
        const float* gp = &g_G[((size_t)t * BS) * JS + jg];
        #pragma unroll
        for (int b2 = 0; b2 < 2; b2++) {
            int b = tb * 2 + b2;
            gate_s[jr][b] = acc[i][b2] + gp[(size_t)b * JS];
        }
    }
    __syncthreads();

    // activation + cell update: 256 cells (8 m x 32 b), 2 per thread
    #pragma unroll
    for (int c2 = 0; c2 < 2; c2++) {
        int cell = tid * 2 + c2;
        int ml = cell >> 5;
        int b  = cell & 31;
        float ig = gate_s[ml][b];
        float fg = gate_s[8 + ml][b];
        float gg = gate_s[16 + ml][b];
        float og = gate_s[24 + ml][b];
        ig = 1.f / (1.f + expf(-ig));
        fg = 1.f / (1.f + expf(-fg));
        og = 1.f / (1.f + expf(-og));
        gg = tanhf(gg);
        int mg = m_base + ml;
        size_t ci = (size_t)b * MS + mg;
        float cn = fg * cstate[ci] + ig * gg;
        float hn = og * tanhf(cn);
        cstate[ci] = cn;
        hout[ci] = hn;
        if (t == TS - 1) hfinal[ci] = hn;
        if (layer == 0) g_hbuf[((size_t)t * BS + b) * MS + mg] = hn;
        else            outs[((size_t)b * TS + t) * MS + mg] = hn;
    }
}

// ------------------------------------------------------------------
extern "C" void kernel_launch(void* const* d_in, const int* in_sizes, int n_in,
                              void* d_out, int out_size)
{
    const float* x   = (const float*)d_in[0];
    const float* h   = (const float*)d_in[1];
    const float* c   = (const float*)d_in[2];
    const float* Wih = (const float*)d_in[3];
    const float* Whh = (const float*)d_in[4];
    const float* bih = (const float*)d_in[5];
    const float* bhh = (const float*)d_in[6];

    float* outs  = (float*)d_out;                       // (B,T,M)
    float* out_h = outs + (size_t)BS * TS * MS;         // (L,B,M)
    float* out_c = out_h + (size_t)LAY * BS * MS;       // (L,B,M)

    init_c_kernel<<<(LAY * BS * MS + 255) / 256, 256>>>(c, out_c);

    for (int l = 0; l < LAY; l++) {
        gemm_input_kernel<<<dim3(JS / 64, (TS * BS) / 64), 256>>>(
            x, Wih + (size_t)l * JS * 1024, bih + (size_t)l * JS, bhh + (size_t)l * JS, l);
        init_h_kernel<<<(BS * MS + 255) / 256, 256>>>(h + (size_t)l * BS * MS);
        for (int t = 0; t < TS; t++) {
            rec_step_kernel<<<MS / 8, 128>>>(
                Whh + (size_t)l * JS * 1024,
                out_c + (size_t)l * BS * MS,
                out_h + (size_t)l * BS * MS,
                outs, t, l);
        }
    }
}

// round 3
// speedup vs baseline: 1.1019x; 1.1010x over previous
#include <cuda_runtime.h>
#include <math.h>
#include <stdint.h>

constexpr int LAY = 2, BS = 32, TS = 256, NS = 1024, MS = 1024, JS = 4096;

__device__ float g_G[(size_t)TS * BS * JS];
__device__ float g_hbuf[(size_t)TS * BS * MS];
__device__ float g_hping[BS * MS];
__device__ float g_hpong[BS * MS];
__device__ unsigned g_cnt;

__device__ __forceinline__ uint32_t smem_u32(const void* p) {
    uint32_t a;
    asm("{ .reg .u64 t; cvta.to.shared.u64 t, %1; cvt.u32.u64 %0, t; }" : "=r"(a) : "l"(p));
    return a;
}
#define CP16(saddr, gptr) \
    asm volatile("cp.async.cg.shared.global [%0], [%1], 16;" :: "r"(saddr), "l"(gptr))
#define CP_COMMIT() asm volatile("cp.async.commit_group;")
#define CP_WAIT1()  asm volatile("cp.async.wait_group 1;")

__global__ void init_h_kernel(const float* __restrict__ h_l) {
    int i = blockIdx.x * blockDim.x + threadIdx.x;
    if (i == 0) g_cnt = 0u;
    if (i < BS * MS) g_hping[i] = h_l[i];
}

// ---------------- input GEMM (unchanged fp32, known-correct) ----------------
__global__ __launch_bounds__(256)
void gemm_input_kernel(const float* __restrict__ x, const float* __restrict__ Wih_l,
                       const float* __restrict__ bih_l, const float* __restrict__ bhh_l, int layer) {
    __shared__ float As[16][68];
    __shared__ float Bs[16][68];
    int tid = threadIdx.x, row0 = blockIdx.y * 64, col0 = blockIdx.x * 64;
    int lrow = tid >> 2, lk = (tid & 3) * 4;
    int r = row0 + lrow;
    const float* Aptr;
    if (layer == 0) { int tt = r >> 5, bb = r & 31; Aptr = x + ((size_t)bb * TS + tt) * NS; }
    else            { Aptr = g_hbuf + (size_t)r * MS; }
    const float* Bptr = Wih_l + (size_t)(col0 + lrow) * 1024;
    int ty = tid >> 4, tx = tid & 15;
    float acc[4][4];
    #pragma unroll
    for (int i = 0; i < 4; i++) for (int j = 0; j < 4; j++) acc[i][j] = 0.f;
    for (int k0 = 0; k0 < 1024; k0 += 16) {
        float4 av = *(const float4*)(Aptr + k0 + lk);
        float4 bv = *(const float4*)(Bptr + k0 + lk);
        __syncthreads();
        As[lk+0][lrow]=av.x; As[lk+1][lrow]=av.y; As[lk+2][lrow]=av.z; As[lk+3][lrow]=av.w;
        Bs[lk+0][lrow]=bv.x; Bs[lk+1][lrow]=bv.y; Bs[lk+2][lrow]=bv.z; Bs[lk+3][lrow]=bv.w;
        __syncthreads();
        #pragma unroll
        for (int k = 0; k < 16; k++) {
            float4 a4 = *(const float4*)&As[k][ty*4];
            float4 b4 = *(const float4*)&Bs[k][tx*4];
            acc[0][0]+=a4.x*b4.x; acc[0][1]+=a4.x*b4.y; acc[0][2]+=a4.x*b4.z; acc[0][3]+=a4.x*b4.w;
            acc[1][0]+=a4.y*b4.x; acc[1][1]+=a4.y*b4.y; acc[1][2]+=a4.y*b4.z; acc[1][3]+=a4.y*b4.w;
            acc[2][0]+=a4.z*b4.x; acc[2][1]+=a4.z*b4.y; acc[2][2]+=a4.z*b4.z; acc[2][3]+=a4.z*b4.w;
            acc[3][0]+=a4.w*b4.x; acc[3][1]+=a4.w*b4.y; acc[3][2]+=a4.w*b4.z; acc[3][3]+=a4.w*b4.w;
        }
    }
    int cbase = col0 + tx * 4;
    float b0=bih_l[cbase+0]+bhh_l[cbase+0], b1=bih_l[cbase+1]+bhh_l[cbase+1];
    float b2=bih_l[cbase+2]+bhh_l[cbase+2], b3=bih_l[cbase+3]+bhh_l[cbase+3];
    #pragma unroll
    for (int i = 0; i < 4; i++) {
        int row = row0 + ty * 4 + i;
        float4 o = {acc[i][0]+b0, acc[i][1]+b1, acc[i][2]+b2, acc[i][3]+b3};
        *(float4*)&g_G[(size_t)row * JS + cbase] = o;
    }
}

// ---------------- persistent recurrence: one kernel per layer ----------------
// 128 CTAs x 256 threads. CTA owns 8 m-units (=32 j rows: gate*8+mloc) x 32 batch.
// c state in registers. h ping-pong in global. Grid barrier between steps.
__global__ __launch_bounds__(256)
void rec_persist(const float* __restrict__ Whh_l, const float* __restrict__ c_in_l,
                 float* __restrict__ out_c_l, float* __restrict__ out_h_l,
                 float* __restrict__ outs, int layer) {
    __shared__ float w_s[2][32 * 68];
    __shared__ float h_s[2][32 * 68];
    __shared__ float gate_s[32 * 33];
    __shared__ float gG_s[32 * 36];

    int tid = threadIdx.x, m_base = blockIdx.x * 8;
    int tj = tid >> 5, tb = tid & 31;          // compute: warp tj -> j rows tj*4..+3, lane -> batch
    int lrow = tid >> 3, kq = tid & 7;         // loader: row 0..31, 8 k-segments
    int gate = lrow >> 3, mloc = lrow & 7;
    const float* wg = Whh_l + ((size_t)(gate * 1024 + m_base + mloc)) * 1024 + kq * 8;
    int ab = tid >> 3, aml = tid & 7;          // activation cell (batch ab, m-local aml)
    int mg = m_base + aml;

    uint32_t s_w = smem_u32(w_s), s_h = smem_u32(h_s), s_gG = smem_u32(gG_s);
    uint32_t wdst = s_w + (uint32_t)(lrow * 68 + kq * 8) * 4;
    uint32_t hdst = s_h + (uint32_t)(lrow * 68 + kq * 8) * 4;
    // G-tile loader role: batch gb, gate gg, half ghf
    int gb = tid >> 3, gg = (tid >> 1) & 3, ghf = tid & 1;
    uint32_t gGdst = s_gG + (uint32_t)(gb * 36 + gg * 8 + ghf * 4) * 4;

    float c_reg = c_in_l[(size_t)ab * MS + mg];
    float hlast = 0.f;
    unsigned nct = gridDim.x;

    for (int t = 0; t < TS; t++) {
        const float* hin  = (t & 1) ? g_hpong : g_hping;
        float*       hout = (t & 1) ? g_hping : g_hpong;
        const float* hg = hin + (size_t)lrow * 1024 + kq * 8;
        // G tile for this step
        const float* gsrc = g_G + ((size_t)(t * 32 + gb)) * JS + gg * 1024 + m_base + ghf * 4;
        CP16(gGdst, gsrc);
        // chunk 0 (same group as G), chunk 1
        CP16(wdst,           wg + 0);  CP16(wdst + 16,           wg + 4);
        CP16(hdst,           hg + 0);  CP16(hdst + 16,           hg + 4);
        CP_COMMIT();
        CP16(wdst + 2176*4,  wg + 64); CP16(wdst + 2176*4 + 16,  wg + 68);
        CP16(hdst + 2176*4,  hg + 64); CP16(hdst + 2176*4 + 16,  hg + 68);
        CP_COMMIT();

        float acc0 = 0.f, acc1 = 0.f, acc2 = 0.f, acc3 = 0.f;
        for (int c = 0; c < 16; c++) {
            CP_WAIT1();
            __syncthreads();
            int buf = c & 1;
            const float* wr = &w_s[buf][(tj * 4) * 68];
            const float* hr = &h_s[buf][tb * 68];
            #pragma unroll
            for (int q = 0; q < 16; q++) {
                float4 h4 = *(const float4*)(hr + q * 4);
                float4 w0 = *(const float4*)(wr + q * 4);
                float4 w1 = *(const float4*)(wr + 68 + q * 4);
                float4 w2 = *(const float4*)(wr + 136 + q * 4);
                float4 w3 = *(const float4*)(wr + 204 + q * 4);
                acc0 += w0.x*h4.x; acc0 += w0.y*h4.y; acc0 += w0.z*h4.z; acc0 += w0.w*h4.w;
                acc1 += w1.x*h4.x; acc1 += w1.y*h4.y; acc1 += w1.z*h4.z; acc1 += w1.w*h4.w;
                acc2 += w2.x*h4.x; acc2 += w2.y*h4.y; acc2 += w2.z*h4.z; acc2 += w2.w*h4.w;
                acc3 += w3.x*h4.x; acc3 += w3.y*h4.y; acc3 += w3.z*h4.z; acc3 += w3.w*h4.w;
            }
            __syncthreads();
            if (c + 2 < 16) {
                int k0 = (c + 2) * 64;
                uint32_t bo = (uint32_t)((c & 1) * 2176 * 4);
                CP16(wdst + bo, wg + k0);  CP16(wdst + bo + 16, wg + k0 + 4);
                CP16(hdst + bo, hg + k0);  CP16(hdst + bo + 16, hg + k0 + 4);
            }
            CP_COMMIT();   // keep group count consistent even on tail iterations
        }

        gate_s[(tj * 4 + 0) * 33 + tb] = acc0;
        gate_s[(tj * 4 + 1) * 33 + tb] = acc1;
        gate_s[(tj * 4 + 2) * 33 + tb] = acc2;
        gate_s[(tj * 4 + 3) * 33 + tb] = acc3;
        __syncthreads();

        float gI = gate_s[ aml       * 33 + ab] + gG_s[ab * 36 + aml];
        float gF = gate_s[(8  + aml) * 33 + ab] + gG_s[ab * 36 + 8  + aml];
        float gC = gate_s[(16 + aml) * 33 + ab] + gG_s[ab * 36 + 16 + aml];
        float gO = gate_s[(24 + aml) * 33 + ab] + gG_s[ab * 36 + 24 + aml];
        float i_ = 1.f / (1.f + expf(-gI));
        float f_ = 1.f / (1.f + expf(-gF));
        float o_ = 1.f / (1.f + expf(-gO));
        float g_ = tanhf(gC);
        c_reg = f_ * c_reg + i_ * g_;
        float hn = o_ * tanhf(c_reg);
        hlast = hn;
        hout[(size_t)ab * 1024 + mg] = hn;
        if (layer == 0) g_hbuf[((size_t)(t * 32 + ab)) * 1024 + mg] = hn;
        else            outs[((size_t)ab * TS + t) * 1024 + mg] = hn;

        if (t < TS - 1) {  // grid barrier (release h writes / acquire for next step)
            __syncthreads();
            if (tid == 0) {
                __threadfence();
                atomicAdd(&g_cnt, 1u);
                unsigned tgt = (unsigned)(t + 1) * nct;
                while (atomicAdd(&g_cnt, 0u) < tgt) __nanosleep(32);
                __threadfence();
            }
            __syncthreads();
        }
    }
    out_c_l[(size_t)ab * 1024 + mg] = c_reg;
    out_h_l[(size_t)ab * 1024 + mg] = hlast;
}

// ------------------------------------------------------------------
extern "C" void kernel_launch(void* const* d_in, const int* in_sizes, int n_in,
                              void* d_out, int out_size) {
    const float* x   = (const float*)d_in[0];
    const float* h   = (const float*)d_in[1];
    const float* c   = (const float*)d_in[2];
    const float* Wih = (const float*)d_in[3];
    const float* Whh = (const float*)d_in[4];
    const float* bih = (const float*)d_in[5];
    const float* bhh = (const float*)d_in[6];

    float* outs  = (float*)d_out;
    float* out_h = outs + (size_t)BS * TS * MS;
    float* out_c = out_h + (size_t)LAY * BS * MS;

    for (int l = 0; l < LAY; l++) {
        gemm_input_kernel<<<dim3(JS / 64, (TS * BS) / 64), 256>>>(
            x, Wih + (size_t)l * JS * 1024, bih + (size_t)l * JS, bhh + (size_t)l * JS, l);
        init_h_kernel<<<(BS * MS + 255) / 256, 256>>>(h + (size_t)l * BS * MS);
        rec_persist<<<128, 256>>>(
            Whh + (size_t)l * JS * 1024,
            c + (size_t)l * BS * MS,
            out_c + (size_t)l * BS * MS,
            out_h + (size_t)l * BS * MS,
            outs, l);
    }
}

// round 5
// speedup vs baseline: 2.5295x; 2.2957x over previous
#include <cuda_runtime.h>
#include <cuda_bf16.h>
#include <math.h>
#include <stdint.h>

constexpr int LAY = 2, BS = 32, TS = 256, NS = 1024, MS = 1024, JS = 4096;

__device__ float g_G[(size_t)TS * BS * JS];       // input-gate precompute rows (t*32+b, j)
__device__ float g_hbuf[(size_t)TS * BS * MS];    // layer-0 h outputs (GEMM input for layer 1)
__device__ __nv_bfloat16 g_hf[2][2][BS * MS];     // [pingpong][hi/lo] B-fragment-packed h
__device__ __nv_bfloat16 g_Wp[(size_t)LAY * 128 * 65536];  // A-fragment-packed Whh hi/lo
__device__ unsigned g_cnt;

// ---------------- helpers ----------------
__device__ __forceinline__ uint32_t smem_u32(const void* p) {
    uint32_t a;
    asm("{ .reg .u64 t; cvta.to.shared.u64 t, %1; cvt.u32.u64 %0, t; }" : "=r"(a) : "l"(p));
    return a;
}
#define CP16(saddr, gptr) \
    asm volatile("cp.async.cg.shared.global [%0], [%1], 16;" :: "r"(saddr), "l"(gptr))
#define CP_COMMIT() asm volatile("cp.async.commit_group;")
#define CP_WAIT1()  asm volatile("cp.async.wait_group 1;")
#define CP_WAIT0()  asm volatile("cp.async.wait_group 0;")

// D(16x8,f32) += A(16x16,bf16,row) * B(16x8,bf16,col)
#define MMA16816(d, a, b) \
    asm volatile("mma.sync.aligned.m16n8k16.row.col.f32.bf16.bf16.f32 " \
        "{%0,%1,%2,%3}, {%4,%5,%6,%7}, {%8,%9}, {%0,%1,%2,%3};" \
        : "+f"((d)[0]), "+f"((d)[1]), "+f"((d)[2]), "+f"((d)[3]) \
        : "r"((a).x), "r"((a).y), "r"((a).z), "r"((a).w), "r"((b).x), "r"((b).y))

// ---------------- one-time conversions ----------------
// Whh -> per-CTA A-fragment pack: [l][jt][ks][mt][hilo][lane][8 bf16]
__global__ void conv_w_kernel(const float* __restrict__ Whh) {
    int idx = blockIdx.x * blockDim.x + threadIdx.x;   // 1,048,576 total
    int lane = idx & 31, mt = (idx >> 5) & 1, ks = (idx >> 6) & 63;
    int jt = (idx >> 12) & 127, l = idx >> 19;
    __nv_bfloat16 hi[8], lo[8];
    #pragma unroll
    for (int q = 0; q < 4; q++) {
        #pragma unroll
        for (int e = 0; e < 2; e++) {
            int rl = (lane >> 2) + (q & 1) * 8;          // row within 16
            int cl = (lane & 3) * 2 + (q >> 1) * 8 + e;  // k within 16
            int jr = mt * 16 + rl;                       // CTA row 0..31 = gate*8+ml
            int j = (jr >> 3) * 1024 + jt * 8 + (jr & 7);
            float v = Whh[((size_t)l * 4096 + j) * 1024 + ks * 16 + cl];
            __nv_bfloat16 h = __float2bfloat16(v);
            hi[q * 2 + e] = h;
            lo[q * 2 + e] = __float2bfloat16(v - __bfloat162float(h));
        }
    }
    size_t o = ((((size_t)(l * 128 + jt) * 64 + ks) * 2 + mt) * 2) * 256 + lane * 8;
    *(uint4*)&g_Wp[o]       = *(uint4*)hi;
    *(uint4*)&g_Wp[o + 256] = *(uint4*)lo;
}

// initial h -> B-fragment pack (pingpong 0); also reset barrier counter
__global__ void init_hf_kernel(const float* __restrict__ h_l) {
    int i = blockIdx.x * blockDim.x + threadIdx.x;
    if (i == 0) g_cnt = 0u;
    if (i >= BS * MS) return;
    int b = i >> 10, m = i & 1023;
    float v = h_l[i];
    __nv_bfloat16 hv = __float2bfloat16(v);
    __nv_bfloat16 lv = __float2bfloat16(v - __bfloat162float(hv));
    int ks = m >> 4, kl = m & 15, nt = b >> 3;
    int ln = (b & 7) * 4 + ((kl & 7) >> 1);
    int slot = (kl >> 3) * 2 + (kl & 1);
    size_t o = ((size_t)(ks * 4 + nt) * 32 + ln) * 4 + slot;
    g_hf[0][0][o] = hv;
    g_hf[0][1][o] = lv;
}

// ---------------- input GEMM (fp32, known-good) ----------------
__global__ __launch_bounds__(256)
void gemm_input_kernel(const float* __restrict__ x, const float* __restrict__ Wih_l,
                       const float* __restrict__ bih_l, const float* __restrict__ bhh_l, int layer) {
    __shared__ float As[16][68];
    __shared__ float Bs[16][68];
    int tid = threadIdx.x, row0 = blockIdx.y * 64, col0 = blockIdx.x * 64;
    int lrow = tid >> 2, lk = (tid & 3) * 4;
    int r = row0 + lrow;
    const float* Aptr;
    if (layer == 0) { int tt = r >> 5, bb = r & 31; Aptr = x + ((size_t)bb * TS + tt) * NS; }
    else            { Aptr = g_hbuf + (size_t)r * MS; }
    const float* Bptr = Wih_l + (size_t)(col0 + lrow) * 1024;
    int ty = tid >> 4, tx = tid & 15;
    float acc[4][4];
    #pragma unroll
    for (int i = 0; i < 4; i++) for (int j = 0; j < 4; j++) acc[i][j] = 0.f;
    for (int k0 = 0; k0 < 1024; k0 += 16) {
        float4 av = *(const float4*)(Aptr + k0 + lk);
        float4 bv = *(const float4*)(Bptr + k0 + lk);
        __syncthreads();
        As[lk+0][lrow]=av.x; As[lk+1][lrow]=av.y; As[lk+2][lrow]=av.z; As[lk+3][lrow]=av.w;
        Bs[lk+0][lrow]=bv.x; Bs[lk+1][lrow]=bv.y; Bs[lk+2][lrow]=bv.z; Bs[lk+3][lrow]=bv.w;
        __syncthreads();
        #pragma unroll
        for (int k = 0; k < 16; k++) {
            float4 a4 = *(const float4*)&As[k][ty*4];
            float4 b4 = *(const float4*)&Bs[k][tx*4];
            acc[0][0]+=a4.x*b4.x; acc[0][1]+=a4.x*b4.y; acc[0][2]+=a4.x*b4.z; acc[0][3]+=a4.x*b4.w;
            acc[1][0]+=a4.y*b4.x; acc[1][1]+=a4.y*b4.y; acc[1][2]+=a4.y*b4.z; acc[1][3]+=a4.y*b4.w;
            acc[2][0]+=a4.z*b4.x; acc[2][1]+=a4.z*b4.y; acc[2][2]+=a4.z*b4.z; acc[2][3]+=a4.z*b4.w;
            acc[3][0]+=a4.w*b4.x; acc[3][1]+=a4.w*b4.y; acc[3][2]+=a4.w*b4.z; acc[3][3]+=a4.w*b4.w;
        }
    }
    int cbase = col0 + tx * 4;
    float b0=bih_l[cbase+0]+bhh_l[cbase+0], b1=bih_l[cbase+1]+bhh_l[cbase+1];
    float b2=bih_l[cbase+2]+bhh_l[cbase+2], b3=bih_l[cbase+3]+bhh_l[cbase+3];
    #pragma unroll
    for (int i = 0; i < 4; i++) {
        int row = row0 + ty * 4 + i;
        float4 o = {acc[i][0]+b0, acc[i][1]+b1, acc[i][2]+b2, acc[i][3]+b3};
        *(float4*)&g_G[(size_t)row * JS + cbase] = o;
    }
}

// ---------------- persistent HMMA recurrence ----------------
// smem: W frags 131072 | B bufs 3x16384 | partials 32768 | G 4096 = 217088
constexpr int OFF_B = 131072, BCHUNK = 16384, OFF_P = 180224, OFF_G = 212992;
constexpr int REC_SMEM = 217088;

__global__ __launch_bounds__(256)
void rec_mma(const float* __restrict__ c_in_l, float* __restrict__ out_c_l,
             float* __restrict__ out_h_l, float* __restrict__ outs, int layer) {
    extern __shared__ char sm[];
    int tid = threadIdx.x, w = tid >> 5, lane = tid & 31;
    int jt = blockIdx.x, m0 = jt * 8;
    uint32_t sb = smem_u32(sm);

    // preload W fragments (resident across all timesteps)
    {
        const char* src = (const char*)g_Wp + (size_t)(layer * 128 + jt) * 131072;
        #pragma unroll
        for (int i = 0; i < 32; i++)
            CP16(sb + (uint32_t)(tid + i * 256) * 16, src + (size_t)(tid + i * 256) * 16);
        CP_COMMIT();
        CP_WAIT0();
    }
    __syncthreads();

    int eb = tid >> 3, ml = tid & 7, m = m0 + ml;
    float creg = c_in_l[(size_t)eb * MS + m];

    // G-tile loader role
    int gb = tid >> 3, gg = (tid >> 1) & 3, gh = tid & 1;
    uint32_t gdst = sb + OFF_G + (uint32_t)(gb * 128 + gg * 32 + gh * 16);

    for (int t = 0; t < TS; t++) {
        int pp = t & 1;
        const char* hH = (const char*)g_hf[pp][0];
        const char* hL = (const char*)g_hf[pp][1];

        // prologue: G + chunk0 (group), chunk1 (group)
        CP16(gdst, g_G + ((size_t)(t * 32 + gb)) * 4096 + gg * 1024 + jt * 8 + gh * 4);
        {
            uint32_t dst = sb + OFF_B + (uint32_t)tid * 32;
            CP16(dst, hH + tid * 32); CP16(dst + 16, hH + tid * 32 + 16);
            CP16(dst + 8192, hL + tid * 32); CP16(dst + 8192 + 16, hL + tid * 32 + 16);
        }
        CP_COMMIT();
        {
            uint32_t dst = sb + OFF_B + BCHUNK + (uint32_t)tid * 32;
            CP16(dst, hH + 8192 + tid * 32); CP16(dst + 16, hH + 8192 + tid * 32 + 16);
            CP16(dst + 8192, hL + 8192 + tid * 32); CP16(dst + 8192 + 16, hL + 8192 + tid * 32 + 16);
        }
        CP_COMMIT();

        float acc[2][4][4];
        #pragma unroll
        for (int a = 0; a < 2; a++) for (int n = 0; n < 4; n++) for (int q = 0; q < 4; q++)
            acc[a][n][q] = 0.f;

        for (int c = 0; c < 8; c++) {
            if (c < 7) { CP_WAIT1(); } else { CP_WAIT0(); }
            __syncthreads();
            if (c < 6) {  // prefetch chunk c+2 into buf (c+2)%3
                uint32_t dst = sb + OFF_B + (uint32_t)((c + 2) % 3) * BCHUNK + (uint32_t)tid * 32;
                const char* sh = hH + (size_t)(c + 2) * 8192 + tid * 32;
                const char* sl = hL + (size_t)(c + 2) * 8192 + tid * 32;
                CP16(dst, sh); CP16(dst + 16, sh + 16);
                CP16(dst + 8192, sl); CP16(dst + 8192 + 16, sl + 16);
                CP_COMMIT();
            }
            // this warp computes slice ks = c*8 + w
            uint32_t abase = (uint32_t)((c * 8 + w) * 2048);
            uint4 aH0 = *(uint4*)(sm + abase +          lane * 16);
            uint4 aL0 = *(uint4*)(sm + abase + 512  +   lane * 16);
            uint4 aH1 = *(uint4*)(sm + abase + 1024 +   lane * 16);
            uint4 aL1 = *(uint4*)(sm + abase + 1536 +   lane * 16);
            uint32_t bbase = (uint32_t)(OFF_B + (c % 3) * BCHUNK + w * 1024);
            #pragma unroll
            for (int nt = 0; nt < 4; nt++) {
                uint2 bH = *(uint2*)(sm + bbase + nt * 256 + lane * 8);
                uint2 bL = *(uint2*)(sm + bbase + 8192 + nt * 256 + lane * 8);
                MMA16816(acc[0][nt], aH0, bH);
                MMA16816(acc[0][nt], aH0, bL);
                MMA16816(acc[0][nt], aL0, bH);
                MMA16816(acc[1][nt], aH1, bH);
                MMA16816(acc[1][nt], aH1, bL);
                MMA16816(acc[1][nt], aL1, bH);
            }
        }

        // stage partials
        #pragma unroll
        for (int mt = 0; mt < 2; mt++) {
            #pragma unroll
            for (int nt = 0; nt < 4; nt++) {
                float4 v = {acc[mt][nt][0], acc[mt][nt][1], acc[mt][nt][2], acc[mt][nt][3]};
                *(float4*)(sm + OFF_P + (((w * 2 + mt) * 4 + nt) * 32 + lane) * 16) = v;
            }
        }
        __syncthreads();

        // reduce 8 warps + add G + activation (thread = cell (eb, ml))
        const float* sPf = (const float*)(sm + OFF_P);
        const float* sGf = (const float*)(sm + OFF_G);
        float gate[4];
        #pragma unroll
        for (int g = 0; g < 4; g++) {
            int jr = g * 8 + ml;
            int mt = jr >> 4, rl = jr & 15;
            int ln = (rl & 7) * 4 + ((eb & 7) >> 1);
            int rg = (rl >> 3) * 2 + (eb & 1);
            int nt = eb >> 3;
            float s = sGf[eb * 32 + jr];
            #pragma unroll
            for (int ww = 0; ww < 8; ww++)
                s += sPf[(((ww * 2 + mt) * 4 + nt) * 32 + ln) * 4 + rg];
            gate[g] = s;
        }
        float i_ = 1.f / (1.f + expf(-gate[0]));
        float f_ = 1.f / (1.f + expf(-gate[1]));
        float g_ = tanhf(gate[2]);
        float o_ = 1.f / (1.f + expf(-gate[3]));
        creg = f_ * creg + i_ * g_;
        float hn = o_ * tanhf(creg);

        // emit h: fragment-packed hi/lo for next step + fp32 for consumers
        {
            __nv_bfloat16 hv = __float2bfloat16(hn);
            __nv_bfloat16 lv = __float2bfloat16(hn - __bfloat162float(hv));
            int ks = m >> 4, kl = m & 15, nt = eb >> 3;
            int ln = (eb & 7) * 4 + ((kl & 7) >> 1);
            int slot = (kl >> 3) * 2 + (kl & 1);
            size_t o = ((size_t)(ks * 4 + nt) * 32 + ln) * 4 + slot;
            g_hf[pp ^ 1][0][o] = hv;
            g_hf[pp ^ 1][1][o] = lv;
        }
        if (layer == 0) g_hbuf[((size_t)(t * 32 + eb)) * MS + m] = hn;
        else            outs[((size_t)eb * TS + t) * MS + m] = hn;
        if (t == TS - 1) out_h_l[(size_t)eb * MS + m] = hn;

        if (t < TS - 1) {
            __syncthreads();
            if (tid == 0) {
                __threadfence();
                atomicAdd(&g_cnt, 1u);
                unsigned tgt = (unsigned)(t + 1) * gridDim.x;
                while (atomicAdd(&g_cnt, 0u) < tgt) __nanosleep(32);
                __threadfence();
            }
            __syncthreads();
        }
    }
    out_c_l[(size_t)eb * MS + m] = creg;
}

// ------------------------------------------------------------------
extern "C" void kernel_launch(void* const* d_in, const int* in_sizes, int n_in,
                              void* d_out, int out_size) {
    const float* x   = (const float*)d_in[0];
    const float* h   = (const float*)d_in[1];
    const float* c   = (const float*)d_in[2];
    const float* Wih = (const float*)d_in[3];
    const float* Whh = (const float*)d_in[4];
    const float* bih = (const float*)d_in[5];
    const float* bhh = (const float*)d_in[6];

    float* outs  = (float*)d_out;
    float* out_h = outs + (size_t)BS * TS * MS;
    float* out_c = out_h + (size_t)LAY * BS * MS;

    cudaFuncSetAttribute(rec_mma, cudaFuncAttributeMaxDynamicSharedMemorySize, REC_SMEM);

    conv_w_kernel<<<4096, 256>>>(Whh);
    for (int l = 0; l < LAY; l++) {
        gemm_input_kernel<<<dim3(JS / 64, (TS * BS) / 64), 256>>>(
            x, Wih + (size_t)l * JS * 1024, bih + (size_t)l * JS, bhh + (size_t)l * JS, l);
        init_hf_kernel<<<(BS * MS + 255) / 256, 256>>>(h + (size_t)l * BS * MS);
        rec_mma<<<128, 256, REC_SMEM>>>(
            c + (size_t)l * BS * MS,
            out_c + (size_t)l * BS * MS,
            out_h + (size_t)l * BS * MS,
            outs, l);
    }
}

// round 6
// speedup vs baseline: 4.1608x; 1.6449x over previous
#include <cuda_runtime.h>
#include <cuda_bf16.h>
#include <math.h>
#include <stdint.h>

constexpr int LAY = 2, BS = 32, TS = 256, NS = 1024, MS = 1024, JS = 4096;

__device__ float g_G[(size_t)TS * BS * JS];       // input-gate precompute rows (t*32+b, j)
__device__ float g_hbuf[(size_t)TS * BS * MS];    // layer-0 h outputs (input for layer-1 GEMM)
__device__ __nv_bfloat16 g_hf[2][2][BS * MS];     // [pingpong][hi/lo] B-fragment-packed h
__device__ __nv_bfloat16 g_Wp[(size_t)LAY * 128 * 65536];  // A-fragment-packed Whh hi/lo
__device__ __nv_bfloat16 g_Af[(size_t)TS * BS * NS * 2];   // A-fragment-packed GEMM input hi/lo
__device__ __nv_bfloat16 g_Bf[(size_t)LAY * JS * NS * 2];  // B-fragment-packed Wih hi/lo
__device__ unsigned g_cnt;

// ---------------- helpers ----------------
__device__ __forceinline__ uint32_t smem_u32(const void* p) {
    uint32_t a;
    asm("{ .reg .u64 t; cvta.to.shared.u64 t, %1; cvt.u32.u64 %0, t; }" : "=r"(a) : "l"(p));
    return a;
}
#define CP16(saddr, gptr) \
    asm volatile("cp.async.cg.shared.global [%0], [%1], 16;" :: "r"(saddr), "l"(gptr))
#define CP_COMMIT() asm volatile("cp.async.commit_group;")
#define CP_WAIT1()  asm volatile("cp.async.wait_group 1;")
#define CP_WAIT0()  asm volatile("cp.async.wait_group 0;")

// D(16x8,f32) += A(16x16,bf16,row) * B(16x8,bf16,col)
#define MMA16816(d, a, b) \
    asm volatile("mma.sync.aligned.m16n8k16.row.col.f32.bf16.bf16.f32 " \
        "{%0,%1,%2,%3}, {%4,%5,%6,%7}, {%8,%9}, {%0,%1,%2,%3};" \
        : "+f"((d)[0]), "+f"((d)[1]), "+f"((d)[2]), "+f"((d)[3]) \
        : "r"((a).x), "r"((a).y), "r"((a).z), "r"((a).w), "r"((b).x), "r"((b).y))

// ---------------- one-time conversions ----------------
// Whh -> per-CTA A-fragment pack (rec): [l][jt][ks][mt][hilo][lane][8 bf16]
__global__ void conv_w_kernel(const float* __restrict__ Whh) {
    int idx = blockIdx.x * blockDim.x + threadIdx.x;
    int lane = idx & 31, mt = (idx >> 5) & 1, ks = (idx >> 6) & 63;
    int jt = (idx >> 12) & 127, l = idx >> 19;
    __nv_bfloat16 hi[8], lo[8];
    #pragma unroll
    for (int q = 0; q < 4; q++) {
        #pragma unroll
        for (int e = 0; e < 2; e++) {
            int rl = (lane >> 2) + (q & 1) * 8;
            int cl = (lane & 3) * 2 + (q >> 1) * 8 + e;
            int jr = mt * 16 + rl;
            int j = (jr >> 3) * 1024 + jt * 8 + (jr & 7);
            float v = Whh[((size_t)l * 4096 + j) * 1024 + ks * 16 + cl];
            __nv_bfloat16 h = __float2bfloat16(v);
            hi[q * 2 + e] = h;
            lo[q * 2 + e] = __float2bfloat16(v - __bfloat162float(h));
        }
    }
    size_t o = ((((size_t)(l * 128 + jt) * 64 + ks) * 2 + mt) * 2) * 256 + lane * 8;
    *(uint4*)&g_Wp[o]       = *(uint4*)hi;
    *(uint4*)&g_Wp[o + 256] = *(uint4*)lo;
}

// GEMM A pack: rows r=t*32+b (layer0 from x, layer1 from g_hbuf).
// layout: [rt 512][ks 64][hilo][lane][8 bf16]
__global__ void conv_a_kernel(const float* __restrict__ x, int layer) {
    int idx = blockIdx.x * blockDim.x + threadIdx.x;   // 1,048,576
    int lane = idx & 31, ks = (idx >> 5) & 63, rt = idx >> 11;
    __nv_bfloat16 hi[8], lo[8];
    #pragma unroll
    for (int q = 0; q < 4; q++) {
        #pragma unroll
        for (int e = 0; e < 2; e++) {
            int rl = (lane >> 2) + (q & 1) * 8;
            int cl = (lane & 3) * 2 + (q >> 1) * 8 + e;
            int row = rt * 16 + rl;
            int k = ks * 16 + cl;
            float v;
            if (layer == 0) { int tt = row >> 5, bb = row & 31; v = x[((size_t)bb * 256 + tt) * 1024 + k]; }
            else            { v = g_hbuf[(size_t)row * 1024 + k]; }
            __nv_bfloat16 h = __float2bfloat16(v);
            hi[q * 2 + e] = h;
            lo[q * 2 + e] = __float2bfloat16(v - __bfloat162float(h));
        }
    }
    size_t o = (((size_t)rt * 64 + ks) * 2) * 256 + lane * 8;
    *(uint4*)&g_Af[o]       = *(uint4*)hi;
    *(uint4*)&g_Af[o + 256] = *(uint4*)lo;
}

// GEMM B pack (Wih, both layers): [l][ct 512][ks 64][hilo][lane][4 bf16]
__global__ void conv_b_kernel(const float* __restrict__ Wih) {
    int idx = blockIdx.x * blockDim.x + threadIdx.x;   // 2,097,152
    int lane = idx & 31, ks = (idx >> 5) & 63, ct = (idx >> 11) & 511, l = idx >> 20;
    int col = ct * 8 + (lane >> 2);
    __nv_bfloat16 hi[4], lo[4];
    #pragma unroll
    for (int s = 0; s < 4; s++) {
        int kl = (s >> 1) * 8 + (lane & 3) * 2 + (s & 1);
        float v = Wih[((size_t)l * 4096 + col) * 1024 + ks * 16 + kl];
        __nv_bfloat16 h = __float2bfloat16(v);
        hi[s] = h;
        lo[s] = __float2bfloat16(v - __bfloat162float(h));
    }
    size_t o = ((((size_t)(l * 512 + ct) * 64 + ks) * 2)) * 128 + lane * 4;
    *(uint2*)&g_Bf[o]       = *(uint2*)hi;
    *(uint2*)&g_Bf[o + 128] = *(uint2*)lo;
}

// initial h -> B-fragment pack (pingpong 0); also reset barrier counter
__global__ void init_hf_kernel(const float* __restrict__ h_l) {
    int i = blockIdx.x * blockDim.x + threadIdx.x;
    if (i == 0) g_cnt = 0u;
    if (i >= BS * MS) return;
    int b = i >> 10, m = i & 1023;
    float v = h_l[i];
    __nv_bfloat16 hv = __float2bfloat16(v);
    __nv_bfloat16 lv = __float2bfloat16(v - __bfloat162float(hv));
    int ks = m >> 4, kl = m & 15, nt = b >> 3;
    int ln = (b & 7) * 4 + ((kl & 7) >> 1);
    int slot = (kl >> 3) * 2 + (kl & 1);
    size_t o = ((size_t)(ks * 4 + nt) * 32 + ln) * 4 + slot;
    g_hf[0][0][o] = hv;
    g_hf[0][1][o] = lv;
}

// ---------------- HMMA input GEMM ----------------
// G[r][j] = A[r][:]·W[j][:] + bias[j].  CTA = 128 rows x 128 cols, K chunks of 64.
// smem: 3 bufs x (A 32KB | B 32KB) + bias 512B.
constexpr int GEMM_SMEM = 3 * 65536 + 512;

__global__ __launch_bounds__(256)
void gemm_mma(int layer, const float* __restrict__ bih_l, const float* __restrict__ bhh_l) {
    extern __shared__ char sm[];
    uint32_t sb = smem_u32(sm);
    int tid = threadIdx.x, w = tid >> 5, lane = tid & 31;
    int bx = blockIdx.x, by = blockIdx.y;
    int wr = w >> 2, wc = w & 3;
    float* sBias = (float*)(sm + 196608);
    if (tid < 128) sBias[tid] = bih_l[bx * 128 + tid] + bhh_l[bx * 128 + tid];

    const size_t lB = (size_t)layer * 512;

    auto issueChunk = [&](int c) {
        uint32_t dst = sb + (uint32_t)(c % 3) * 65536;
        int ks0 = c * 4;
        #pragma unroll
        for (int i = 0; i < 8; i++) {   // A: 2048 16B units
            int u = tid + i * 256;
            int rt = u >> 8, ks = (u >> 6) & 3, hl = (u >> 5) & 1, ln = u & 31;
            const char* src = (const char*)g_Af +
                ((((size_t)(by * 8 + rt)) * 64 + ks0 + ks) * 2 + hl) * 512 + ln * 16;
            CP16(dst + (uint32_t)u * 16, src);
        }
        #pragma unroll
        for (int i = 0; i < 8; i++) {   // B: 2048 16B units
            int u = tid + i * 256;
            int ct = u >> 7, ks = (u >> 5) & 3, hl = (u >> 4) & 1, un = u & 15;
            const char* src = (const char*)g_Bf +
                (((lB + bx * 16 + ct) * 64 + ks0 + ks) * 2 + hl) * 256 + un * 16;
            CP16(dst + 32768 + (uint32_t)u * 16, src);
        }
        CP_COMMIT();
    };

    issueChunk(0);
    issueChunk(1);

    float acc[4][4][4];
    #pragma unroll
    for (int a = 0; a < 4; a++) for (int b = 0; b < 4; b++) for (int q = 0; q < 4; q++)
        acc[a][b][q] = 0.f;

    for (int c = 0; c < 16; c++) {
        if (c < 15) { CP_WAIT1(); } else { CP_WAIT0(); }
        __syncthreads();
        if (c < 14) issueChunk(c + 2);
        const char* bufA = sm + (c % 3) * 65536;
        const char* bufB = bufA + 32768;
        #pragma unroll
        for (int ks = 0; ks < 4; ks++) {
            uint4 aH[4], aL[4];
            #pragma unroll
            for (int mt = 0; mt < 4; mt++) {
                int rt = wr * 4 + mt;
                aH[mt] = *(const uint4*)(bufA + (((rt * 4 + ks) * 2 + 0) * 512) + lane * 16);
                aL[mt] = *(const uint4*)(bufA + (((rt * 4 + ks) * 2 + 1) * 512) + lane * 16);
            }
            #pragma unroll
            for (int nt = 0; nt < 4; nt++) {
                int ct = wc * 4 + nt;
                uint2 bH = *(const uint2*)(bufB + (((ct * 4 + ks) * 2 + 0) * 256) + lane * 8);
                uint2 bL = *(const uint2*)(bufB + (((ct * 4 + ks) * 2 + 1) * 256) + lane * 8);
                #pragma unroll
                for (int mt = 0; mt < 4; mt++) {
                    MMA16816(acc[mt][nt], aH[mt], bH);
                    MMA16816(acc[mt][nt], aH[mt], bL);
                    MMA16816(acc[mt][nt], aL[mt], bH);
                }
            }
        }
    }

    // epilogue: bias + store to g_G
    int r0 = by * 128 + wr * 64;
    int c0g = bx * 128 + wc * 32;
    #pragma unroll
    for (int mt = 0; mt < 4; mt++) {
        #pragma unroll
        for (int nt = 0; nt < 4; nt++) {
            int row = r0 + mt * 16 + (lane >> 2);
            int col = c0g + nt * 8 + (lane & 3) * 2;
            int lc = wc * 32 + nt * 8 + (lane & 3) * 2;
            float b0 = sBias[lc], b1 = sBias[lc + 1];
            float2 v0 = {acc[mt][nt][0] + b0, acc[mt][nt][1] + b1};
            float2 v1 = {acc[mt][nt][2] + b0, acc[mt][nt][3] + b1};
            *(float2*)&g_G[(size_t)row * 4096 + col] = v0;
            *(float2*)&g_G[(size_t)(row + 8) * 4096 + col] = v1;
        }
    }
}

// ---------------- persistent HMMA recurrence (unchanged, proven) ----------------
constexpr int OFF_B = 131072, BCHUNK = 16384, OFF_P = 180224, OFF_G = 212992;
constexpr int REC_SMEM = 217088;

__global__ __launch_bounds__(256)
void rec_mma(const float* __restrict__ c_in_l, float* __restrict__ out_c_l,
             float* __restrict__ out_h_l, float* __restrict__ outs, int layer) {
    extern __shared__ char sm[];
    int tid = threadIdx.x, w = tid >> 5, lane = tid & 31;
    int jt = blockIdx.x, m0 = jt * 8;
    uint32_t sb = smem_u32(sm);

    {
        const char* src = (const char*)g_Wp + (size_t)(layer * 128 + jt) * 131072;
        #pragma unroll
        for (int i = 0; i < 32; i++)
            CP16(sb + (uint32_t)(tid + i * 256) * 16, src + (size_t)(tid + i * 256) * 16);
        CP_COMMIT();
        CP_WAIT0();
    }
    __syncthreads();

    int eb = tid >> 3, ml = tid & 7, m = m0 + ml;
    float creg = c_in_l[(size_t)eb * MS + m];

    int gb = tid >> 3, gg = (tid >> 1) & 3, gh = tid & 1;
    uint32_t gdst = sb + OFF_G + (uint32_t)(gb * 128 + gg * 32 + gh * 16);

    for (int t = 0; t < TS; t++) {
        int pp = t & 1;
        const char* hH = (const char*)g_hf[pp][0];
        const char* hL = (const char*)g_hf[pp][1];

        CP16(gdst, g_G + ((size_t)(t * 32 + gb)) * 4096 + gg * 1024 + jt * 8 + gh * 4);
        {
            uint32_t dst = sb + OFF_B + (uint32_t)tid * 32;
            CP16(dst, hH + tid * 32); CP16(dst + 16, hH + tid * 32 + 16);
            CP16(dst + 8192, hL + tid * 32); CP16(dst + 8192 + 16, hL + tid * 32 + 16);
        }
        CP_COMMIT();
        {
            uint32_t dst = sb + OFF_B + BCHUNK + (uint32_t)tid * 32;
            CP16(dst, hH + 8192 + tid * 32); CP16(dst + 16, hH + 8192 + tid * 32 + 16);
            CP16(dst + 8192, hL + 8192 + tid * 32); CP16(dst + 8192 + 16, hL + 8192 + tid * 32 + 16);
        }
        CP_COMMIT();

        float acc[2][4][4];
        #pragma unroll
        for (int a = 0; a < 2; a++) for (int n = 0; n < 4; n++) for (int q = 0; q < 4; q++)
            acc[a][n][q] = 0.f;

        for (int c = 0; c < 8; c++) {
            if (c < 7) { CP_WAIT1(); } else { CP_WAIT0(); }
            __syncthreads();
            if (c < 6) {
                uint32_t dst = sb + OFF_B + (uint32_t)((c + 2) % 3) * BCHUNK + (uint32_t)tid * 32;
                const char* sh = hH + (size_t)(c + 2) * 8192 + tid * 32;
                const char* sl = hL + (size_t)(c + 2) * 8192 + tid * 32;
                CP16(dst, sh); CP16(dst + 16, sh + 16);
                CP16(dst + 8192, sl); CP16(dst + 8192 + 16, sl + 16);
                CP_COMMIT();
            }
            uint32_t abase = (uint32_t)((c * 8 + w) * 2048);
            uint4 aH0 = *(uint4*)(sm + abase +          lane * 16);
            uint4 aL0 = *(uint4*)(sm + abase + 512  +   lane * 16);
            uint4 aH1 = *(uint4*)(sm + abase + 1024 +   lane * 16);
            uint4 aL1 = *(uint4*)(sm + abase + 1536 +   lane * 16);
            uint32_t bbase = (uint32_t)(OFF_B + (c % 3) * BCHUNK + w * 1024);
            #pragma unroll
            for (int nt = 0; nt < 4; nt++) {
                uint2 bH = *(uint2*)(sm + bbase + nt * 256 + lane * 8);
                uint2 bL = *(uint2*)(sm + bbase + 8192 + nt * 256 + lane * 8);
                MMA16816(acc[0][nt], aH0, bH);
                MMA16816(acc[0][nt], aH0, bL);
                MMA16816(acc[0][nt], aL0, bH);
                MMA16816(acc[1][nt], aH1, bH);
                MMA16816(acc[1][nt], aH1, bL);
                MMA16816(acc[1][nt], aL1, bH);
            }
        }

        #pragma unroll
        for (int mt = 0; mt < 2; mt++) {
            #pragma unroll
            for (int nt = 0; nt < 4; nt++) {
                float4 v = {acc[mt][nt][0], acc[mt][nt][1], acc[mt][nt][2], acc[mt][nt][3]};
                *(float4*)(sm + OFF_P + (((w * 2 + mt) * 4 + nt) * 32 + lane) * 16) = v;
            }
        }
        __syncthreads();

        const float* sPf = (const float*)(sm + OFF_P);
        const float* sGf = (const float*)(sm + OFF_G);
        float gate[4];
        #pragma unroll
        for (int g = 0; g < 4; g++) {
            int jr = g * 8 + ml;
            int mt = jr >> 4, rl = jr & 15;
            int ln = (rl & 7) * 4 + ((eb & 7) >> 1);
            int rg = (rl >> 3) * 2 + (eb & 1);
            int nt = eb >> 3;
            float s = sGf[eb * 32 + jr];
            #pragma unroll
            for (int ww = 0; ww < 8; ww++)
                s += sPf[(((ww * 2 + mt) * 4 + nt) * 32 + ln) * 4 + rg];
            gate[g] = s;
        }
        float i_ = 1.f / (1.f + expf(-gate[0]));
        float f_ = 1.f / (1.f + expf(-gate[1]));
        float g_ = tanhf(gate[2]);
        float o_ = 1.f / (1.f + expf(-gate[3]));
        creg = f_ * creg + i_ * g_;
        float hn = o_ * tanhf(creg);

        {
            __nv_bfloat16 hv = __float2bfloat16(hn);
            __nv_bfloat16 lv = __float2bfloat16(hn - __bfloat162float(hv));
            int ks = m >> 4, kl = m & 15, nt = eb >> 3;
            int ln = (eb & 7) * 4 + ((kl & 7) >> 1);
            int slot = (kl >> 3) * 2 + (kl & 1);
            size_t o = ((size_t)(ks * 4 + nt) * 32 + ln) * 4 + slot;
            g_hf[pp ^ 1][0][o] = hv;
            g_hf[pp ^ 1][1][o] = lv;
        }
        if (layer == 0) g_hbuf[((size_t)(t * 32 + eb)) * MS + m] = hn;
        else            outs[((size_t)eb * TS + t) * MS + m] = hn;
        if (t == TS - 1) out_h_l[(size_t)eb * MS + m] = hn;

        if (t < TS - 1) {
            __syncthreads();
            if (tid == 0) {
                __threadfence();
                atomicAdd(&g_cnt, 1u);
                unsigned tgt = (unsigned)(t + 1) * gridDim.x;
                while (atomicAdd(&g_cnt, 0u) < tgt) __nanosleep(32);
                __threadfence();
            }
            __syncthreads();
        }
    }
    out_c_l[(size_t)eb * MS + m] = creg;
}

// ------------------------------------------------------------------
extern "C" void kernel_launch(void* const* d_in, const int* in_sizes, int n_in,
                              void* d_out, int out_size) {
    const float* x   = (const float*)d_in[0];
    const float* h   = (const float*)d_in[1];
    const float* c   = (const float*)d_in[2];
    const float* Wih = (const float*)d_in[3];
    const float* Whh = (const float*)d_in[4];
    const float* bih = (const float*)d_in[5];
    const float* bhh = (const float*)d_in[6];

    float* outs  = (float*)d_out;
    float* out_h = outs + (size_t)BS * TS * MS;
    float* out_c = out_h + (size_t)LAY * BS * MS;

    cudaFuncSetAttribute(rec_mma, cudaFuncAttributeMaxDynamicSharedMemorySize, REC_SMEM);
    cudaFuncSetAttribute(gemm_mma, cudaFuncAttributeMaxDynamicSharedMemorySize, GEMM_SMEM);

    conv_w_kernel<<<4096, 256>>>(Whh);
    conv_b_kernel<<<8192, 256>>>(Wih);
    for (int l = 0; l < LAY; l++) {
        conv_a_kernel<<<4096, 256>>>(x, l);
        gemm_mma<<<dim3(32, 64), 256, GEMM_SMEM>>>(
            l, bih + (size_t)l * JS, bhh + (size_t)l * JS);
        init_hf_kernel<<<(BS * MS + 255) / 256, 256>>>(h + (size_t)l * BS * MS);
        rec_mma<<<128, 256, REC_SMEM>>>(
            c + (size_t)l * BS * MS,
            out_c + (size_t)l * BS * MS,
            out_h + (size_t)l * BS * MS,
            outs, l);
    }
}

// round 7
// speedup vs baseline: 4.5643x; 1.0970x over previous
#include <cuda_runtime.h>
#include <cuda_bf16.h>
#include <math.h>
#include <stdint.h>

constexpr int LAY = 2, BS = 32, TS = 256, NS = 1024, MS = 1024, JS = 4096;

__device__ float g_G[(size_t)TS * BS * JS];       // input-gate precompute rows (t*32+b, j)
__device__ float g_hbuf[(size_t)TS * BS * MS];    // layer-0 h outputs (input for layer-1 GEMM)
__device__ __nv_bfloat16 g_hf[2][2][BS * MS];     // [pingpong][hi/lo] B-fragment-packed h
__device__ __nv_bfloat16 g_Wp[(size_t)LAY * 128 * 65536];  // A-fragment-packed Whh hi/lo
__device__ __nv_bfloat16 g_Af[(size_t)TS * BS * NS * 2];   // A-fragment-packed GEMM input hi/lo
__device__ __nv_bfloat16 g_Bf[(size_t)LAY * JS * NS * 2];  // B-fragment-packed Wih hi/lo
__device__ unsigned g_cnt;

// ---------------- helpers ----------------
__device__ __forceinline__ uint32_t smem_u32(const void* p) {
    uint32_t a;
    asm("{ .reg .u64 t; cvta.to.shared.u64 t, %1; cvt.u32.u64 %0, t; }" : "=r"(a) : "l"(p));
    return a;
}
#define CP16(saddr, gptr) \
    asm volatile("cp.async.cg.shared.global [%0], [%1], 16;" :: "r"(saddr), "l"(gptr))
#define CP_COMMIT() asm volatile("cp.async.commit_group;")
#define CP_WAIT1()  asm volatile("cp.async.wait_group 1;")
#define CP_WAIT0()  asm volatile("cp.async.wait_group 0;")

// D(16x8,f32) += A(16x16,bf16,row) * B(16x8,bf16,col)
#define MMA16816(d, a, b) \
    asm volatile("mma.sync.aligned.m16n8k16.row.col.f32.bf16.bf16.f32 " \
        "{%0,%1,%2,%3}, {%4,%5,%6,%7}, {%8,%9}, {%0,%1,%2,%3};" \
        : "+f"((d)[0]), "+f"((d)[1]), "+f"((d)[2]), "+f"((d)[3]) \
        : "r"((a).x), "r"((a).y), "r"((a).z), "r"((a).w), "r"((b).x), "r"((b).y))

// ---------------- one-time conversions ----------------
// Whh -> per-CTA A-fragment pack (rec): [l][jt][ks][mt][hilo][lane][8 bf16]
__global__ void conv_w_kernel(const float* __restrict__ Whh) {
    int idx = blockIdx.x * blockDim.x + threadIdx.x;
    int lane = idx & 31, mt = (idx >> 5) & 1, ks = (idx >> 6) & 63;
    int jt = (idx >> 12) & 127, l = idx >> 19;
    __nv_bfloat16 hi[8], lo[8];
    #pragma unroll
    for (int q = 0; q < 4; q++) {
        #pragma unroll
        for (int e = 0; e < 2; e++) {
            int rl = (lane >> 2) + (q & 1) * 8;
            int cl = (lane & 3) * 2 + (q >> 1) * 8 + e;
            int jr = mt * 16 + rl;
            int j = (jr >> 3) * 1024 + jt * 8 + (jr & 7);
            float v = Whh[((size_t)l * 4096 + j) * 1024 + ks * 16 + cl];
            __nv_bfloat16 h = __float2bfloat16(v);
            hi[q * 2 + e] = h;
            lo[q * 2 + e] = __float2bfloat16(v - __bfloat162float(h));
        }
    }
    size_t o = ((((size_t)(l * 128 + jt) * 64 + ks) * 2 + mt) * 2) * 256 + lane * 8;
    *(uint4*)&g_Wp[o]       = *(uint4*)hi;
    *(uint4*)&g_Wp[o + 256] = *(uint4*)lo;
}

// GEMM A pack: rows r=t*32+b (layer0 from x, layer1 from g_hbuf).
__global__ void conv_a_kernel(const float* __restrict__ x, int layer) {
    int idx = blockIdx.x * blockDim.x + threadIdx.x;   // 1,048,576
    int lane = idx & 31, ks = (idx >> 5) & 63, rt = idx >> 11;
    __nv_bfloat16 hi[8], lo[8];
    #pragma unroll
    for (int q = 0; q < 4; q++) {
        #pragma unroll
        for (int e = 0; e < 2; e++) {
            int rl = (lane >> 2) + (q & 1) * 8;
            int cl = (lane & 3) * 2 + (q >> 1) * 8 + e;
            int row = rt * 16 + rl;
            int k = ks * 16 + cl;
            float v;
            if (layer == 0) { int tt = row >> 5, bb = row & 31; v = x[((size_t)bb * 256 + tt) * 1024 + k]; }
            else            { v = g_hbuf[(size_t)row * 1024 + k]; }
            __nv_bfloat16 h = __float2bfloat16(v);
            hi[q * 2 + e] = h;
            lo[q * 2 + e] = __float2bfloat16(v - __bfloat162float(h));
        }
    }
    size_t o = (((size_t)rt * 64 + ks) * 2) * 256 + lane * 8;
    *(uint4*)&g_Af[o]       = *(uint4*)hi;
    *(uint4*)&g_Af[o + 256] = *(uint4*)lo;
}

// GEMM B pack (Wih, both layers): [l][ct 512][ks 64][hilo][lane][4 bf16]
__global__ void conv_b_kernel(const float* __restrict__ Wih) {
    int idx = blockIdx.x * blockDim.x + threadIdx.x;   // 2,097,152
    int lane = idx & 31, ks = (idx >> 5) & 63, ct = (idx >> 11) & 511, l = idx >> 20;
    int col = ct * 8 + (lane >> 2);
    __nv_bfloat16 hi[4], lo[4];
    #pragma unroll
    for (int s = 0; s < 4; s++) {
        int kl = (s >> 1) * 8 + (lane & 3) * 2 + (s & 1);
        float v = Wih[((size_t)l * 4096 + col) * 1024 + ks * 16 + kl];
        __nv_bfloat16 h = __float2bfloat16(v);
        hi[s] = h;
        lo[s] = __float2bfloat16(v - __bfloat162float(h));
    }
    size_t o = ((((size_t)(l * 512 + ct) * 64 + ks) * 2)) * 128 + lane * 4;
    *(uint2*)&g_Bf[o]       = *(uint2*)hi;
    *(uint2*)&g_Bf[o + 128] = *(uint2*)lo;
}

// initial h -> B-fragment pack (pingpong 0); also reset barrier counter
__global__ void init_hf_kernel(const float* __restrict__ h_l) {
    int i = blockIdx.x * blockDim.x + threadIdx.x;
    if (i == 0) g_cnt = 0u;
    if (i >= BS * MS) return;
    int b = i >> 10, m = i & 1023;
    float v = h_l[i];
    __nv_bfloat16 hv = __float2bfloat16(v);
    __nv_bfloat16 lv = __float2bfloat16(v - __bfloat162float(hv));
    int ks = m >> 4, kl = m & 15, nt = b >> 3;
    int ln = (b & 7) * 4 + ((kl & 7) >> 1);
    int slot = (kl >> 3) * 2 + (kl & 1);
    size_t o = ((size_t)(ks * 4 + nt) * 32 + ln) * 4 + slot;
    g_hf[0][0][o] = hv;
    g_hf[0][1][o] = lv;
}

// ---------------- HMMA input GEMM (proven) ----------------
constexpr int GEMM_SMEM = 3 * 65536 + 512;

__global__ __launch_bounds__(256)
void gemm_mma(int layer, const float* __restrict__ bih_l, const float* __restrict__ bhh_l) {
    extern __shared__ char sm[];
    uint32_t sb = smem_u32(sm);
    int tid = threadIdx.x, w = tid >> 5, lane = tid & 31;
    int bx = blockIdx.x, by = blockIdx.y;
    int wr = w >> 2, wc = w & 3;
    float* sBias = (float*)(sm + 196608);
    if (tid < 128) sBias[tid] = bih_l[bx * 128 + tid] + bhh_l[bx * 128 + tid];

    const size_t lB = (size_t)layer * 512;

    auto issueChunk = [&](int c) {
        uint32_t dst = sb + (uint32_t)(c % 3) * 65536;
        int ks0 = c * 4;
        #pragma unroll
        for (int i = 0; i < 8; i++) {
            int u = tid + i * 256;
            int rt = u >> 8, ks = (u >> 6) & 3, hl = (u >> 5) & 1, ln = u & 31;
            const char* src = (const char*)g_Af +
                ((((size_t)(by * 8 + rt)) * 64 + ks0 + ks) * 2 + hl) * 512 + ln * 16;
            CP16(dst + (uint32_t)u * 16, src);
        }
        #pragma unroll
        for (int i = 0; i < 8; i++) {
            int u = tid + i * 256;
            int ct = u >> 7, ks = (u >> 5) & 3, hl = (u >> 4) & 1, un = u & 15;
            const char* src = (const char*)g_Bf +
                (((lB + bx * 16 + ct) * 64 + ks0 + ks) * 2 + hl) * 256 + un * 16;
            CP16(dst + 32768 + (uint32_t)u * 16, src);
        }
        CP_COMMIT();
    };

    issueChunk(0);
    issueChunk(1);

    float acc[4][4][4];
    #pragma unroll
    for (int a = 0; a < 4; a++) for (int b = 0; b < 4; b++) for (int q = 0; q < 4; q++)
        acc[a][b][q] = 0.f;

    for (int c = 0; c < 16; c++) {
        if (c < 15) { CP_WAIT1(); } else { CP_WAIT0(); }
        __syncthreads();
        if (c < 14) issueChunk(c + 2);
        const char* bufA = sm + (c % 3) * 65536;
        const char* bufB = bufA + 32768;
        #pragma unroll
        for (int ks = 0; ks < 4; ks++) {
            uint4 aH[4], aL[4];
            #pragma unroll
            for (int mt = 0; mt < 4; mt++) {
                int rt = wr * 4 + mt;
                aH[mt] = *(const uint4*)(bufA + (((rt * 4 + ks) * 2 + 0) * 512) + lane * 16);
                aL[mt] = *(const uint4*)(bufA + (((rt * 4 + ks) * 2 + 1) * 512) + lane * 16);
            }
            #pragma unroll
            for (int nt = 0; nt < 4; nt++) {
                int ct = wc * 4 + nt;
                uint2 bH = *(const uint2*)(bufB + (((ct * 4 + ks) * 2 + 0) * 256) + lane * 8);
                uint2 bL = *(const uint2*)(bufB + (((ct * 4 + ks) * 2 + 1) * 256) + lane * 8);
                #pragma unroll
                for (int mt = 0; mt < 4; mt++) {
                    MMA16816(acc[mt][nt], aH[mt], bH);
                    MMA16816(acc[mt][nt], aH[mt], bL);
                    MMA16816(acc[mt][nt], aL[mt], bH);
                }
            }
        }
    }

    int r0 = by * 128 + wr * 64;
    int c0g = bx * 128 + wc * 32;
    #pragma unroll
    for (int mt = 0; mt < 4; mt++) {
        #pragma unroll
        for (int nt = 0; nt < 4; nt++) {
            int row = r0 + mt * 16 + (lane >> 2);
            int col = c0g + nt * 8 + (lane & 3) * 2;
            int lc = wc * 32 + nt * 8 + (lane & 3) * 2;
            float b0 = sBias[lc], b1 = sBias[lc + 1];
            float2 v0 = {acc[mt][nt][0] + b0, acc[mt][nt][1] + b1};
            float2 v1 = {acc[mt][nt][2] + b0, acc[mt][nt][3] + b1};
            *(float2*)&g_G[(size_t)row * 4096 + col] = v0;
            *(float2*)&g_G[(size_t)(row + 8) * 4096 + col] = v1;
        }
    }
}

// ---------------- persistent HMMA recurrence v3 ----------------
// 128 CTAs x 512 threads (16 warps, 4/SMSP). W resident 128KB.
// h: 4 chunks of k=256 (32KB each: 16K hi + 16K lo), 2 buffers.
// G in registers. Partials two-phase into 8 slots (32KB).
constexpr int OFF_B = 131072, BCHUNK = 32768, OFF_P = 196608;
constexpr int REC_SMEM = 229376;

__global__ __launch_bounds__(512)
void rec_mma(const float* __restrict__ c_in_l, float* __restrict__ out_c_l,
             float* __restrict__ out_h_l, float* __restrict__ outs, int layer) {
    extern __shared__ char sm[];
    int tid = threadIdx.x, w = tid >> 5, lane = tid & 31;
    int jt = blockIdx.x, m0 = jt * 8;
    uint32_t sb = smem_u32(sm);

    // preload W fragments (resident all timesteps): 8192 units / 512 thr
    {
        const char* src = (const char*)g_Wp + (size_t)(layer * 128 + jt) * 131072;
        #pragma unroll
        for (int i = 0; i < 16; i++)
            CP16(sb + (uint32_t)(tid + i * 512) * 16, src + (size_t)(tid + i * 512) * 16);
        CP_COMMIT();
        CP_WAIT0();
    }
    __syncthreads();

    int eb = (tid >> 3) & 31, ml = tid & 7, m = m0 + ml;
    float creg = 0.f;
    if (tid < 256) creg = c_in_l[(size_t)eb * MS + m];

    for (int t = 0; t < TS; t++) {
        int pp = t & 1;
        const char* hH = (const char*)g_hf[pp][0];
        const char* hL = (const char*)g_hf[pp][1];

        // G prefetch into registers (constant during kernel; hidden by chunk loop)
        float Gr[4];
        if (tid < 256) {
            #pragma unroll
            for (int g = 0; g < 4; g++)
                Gr[g] = __ldg(&g_G[((size_t)(t * 32 + eb)) * 4096 + g * 1024 + jt * 8 + ml]);
        }

        // issue h chunk c into buffer buf: hi 16KB + lo 16KB (2 units each/thread)
        auto issueH = [&](int c, int buf) {
            uint32_t dst = sb + OFF_B + (uint32_t)buf * BCHUNK;
            const char* sh = hH + (size_t)c * 16384;
            const char* sl = hL + (size_t)c * 16384;
            #pragma unroll
            for (int i = 0; i < 2; i++) {
                uint32_t u16 = (uint32_t)(tid + i * 512) * 16;
                CP16(dst + u16, sh + u16);
                CP16(dst + 16384 + u16, sl + u16);
            }
            CP_COMMIT();
        };

        issueH(0, 0);
        issueH(1, 1);

        float acc[2][4][4];
        #pragma unroll
        for (int a = 0; a < 2; a++) for (int n = 0; n < 4; n++) for (int q = 0; q < 4; q++)
            acc[a][n][q] = 0.f;

        #pragma unroll
        for (int c = 0; c < 4; c++) {
            if (c == 0) { CP_WAIT1(); } else { CP_WAIT0(); }
            __syncthreads();   // chunk c visible; buffer (c&1) free for reuse by all warps
            if (c >= 1 && c + 1 < 4) issueH(c + 1, (c + 1) & 1);

            int ks = c * 16 + w;    // this warp's k-slice
            uint32_t abase = (uint32_t)(ks * 2048);
            uint4 aH0 = *(uint4*)(sm + abase +        lane * 16);
            uint4 aL0 = *(uint4*)(sm + abase + 512  + lane * 16);
            uint4 aH1 = *(uint4*)(sm + abase + 1024 + lane * 16);
            uint4 aL1 = *(uint4*)(sm + abase + 1536 + lane * 16);
            uint32_t bbase = (uint32_t)(OFF_B + (c & 1) * BCHUNK + w * 1024);
            #pragma unroll
            for (int nt = 0; nt < 4; nt++) {
                uint2 bH = *(uint2*)(sm + bbase + nt * 256 + lane * 8);
                uint2 bL = *(uint2*)(sm + bbase + 16384 + nt * 256 + lane * 8);
                MMA16816(acc[0][nt], aH0, bH);
                MMA16816(acc[0][nt], aH0, bL);
                MMA16816(acc[0][nt], aL0, bH);
                MMA16816(acc[1][nt], aH1, bH);
                MMA16816(acc[1][nt], aH1, bL);
                MMA16816(acc[1][nt], aL1, bH);
            }
        }

        // two-phase partial staging: warps 0-7 store, warps 8-15 fold in
        if (w < 8) {
            #pragma unroll
            for (int mt = 0; mt < 2; mt++)
                #pragma unroll
                for (int nt = 0; nt < 4; nt++) {
                    float4 v = {acc[mt][nt][0], acc[mt][nt][1], acc[mt][nt][2], acc[mt][nt][3]};
                    *(float4*)(sm + OFF_P + (((w * 2 + mt) * 4 + nt) * 32 + lane) * 16) = v;
                }
        }
        __syncthreads();
        if (w >= 8) {
            int ws = w - 8;
            #pragma unroll
            for (int mt = 0; mt < 2; mt++)
                #pragma unroll
                for (int nt = 0; nt < 4; nt++) {
                    float4* p = (float4*)(sm + OFF_P + (((ws * 2 + mt) * 4 + nt) * 32 + lane) * 16);
                    float4 v = *p;
                    v.x += acc[mt][nt][0]; v.y += acc[mt][nt][1];
                    v.z += acc[mt][nt][2]; v.w += acc[mt][nt][3];
                    *p = v;
                }
        }
        __syncthreads();

        if (tid < 256) {
            const float* sPf = (const float*)(sm + OFF_P);
            float gate[4];
            #pragma unroll
            for (int g = 0; g < 4; g++) {
                int jr = g * 8 + ml;
                int mt = jr >> 4, rl = jr & 15;
                int ln = (rl & 7) * 4 + ((eb & 7) >> 1);
                int rg = (rl >> 3) * 2 + (eb & 1);
                int nt = eb >> 3;
                float s = Gr[g];
                #pragma unroll
                for (int ww = 0; ww < 8; ww++)
                    s += sPf[(((ww * 2 + mt) * 4 + nt) * 32 + ln) * 4 + rg];
                gate[g] = s;
            }
            float i_ = 1.f / (1.f + expf(-gate[0]));
            float f_ = 1.f / (1.f + expf(-gate[1]));
            float g_ = tanhf(gate[2]);
            float o_ = 1.f / (1.f + expf(-gate[3]));
            creg = f_ * creg + i_ * g_;
            float hn = o_ * tanhf(creg);

            __nv_bfloat16 hv = __float2bfloat16(hn);
            __nv_bfloat16 lv = __float2bfloat16(hn - __bfloat162float(hv));
            int ks = m >> 4, kl = m & 15, nt = eb >> 3;
            int ln = (eb & 7) * 4 + ((kl & 7) >> 1);
            int slot = (kl >> 3) * 2 + (kl & 1);
            size_t o = ((size_t)(ks * 4 + nt) * 32 + ln) * 4 + slot;
            g_hf[pp ^ 1][0][o] = hv;
            g_hf[pp ^ 1][1][o] = lv;

            if (layer == 0) g_hbuf[((size_t)(t * 32 + eb)) * MS + m] = hn;
            else            outs[((size_t)eb * TS + t) * MS + m] = hn;
            if (t == TS - 1) out_h_l[(size_t)eb * MS + m] = hn;
        }

        if (t < TS - 1) {   // grid barrier: release/acquire, no fence/RMW-poll
            __syncthreads();
            if (tid == 0) {
                unsigned tgt = (unsigned)(t + 1) * gridDim.x;
                asm volatile("red.release.gpu.global.add.u32 [%0], %1;"
                             :: "l"(&g_cnt), "r"(1u) : "memory");
                unsigned v;
                do {
                    asm volatile("ld.acquire.gpu.global.u32 %0, [%1];"
                                 : "=r"(v) : "l"(&g_cnt) : "memory");
                } while (v < tgt);
            }
            __syncthreads();
        }
    }
    if (tid < 256) out_c_l[(size_t)eb * MS + m] = creg;
}

// ------------------------------------------------------------------
extern "C" void kernel_launch(void* const* d_in, const int* in_sizes, int n_in,
                              void* d_out, int out_size) {
    const float* x   = (const float*)d_in[0];
    const float* h   = (const float*)d_in[1];
    const float* c   = (const float*)d_in[2];
    const float* Wih = (const float*)d_in[3];
    const float* Whh = (const float*)d_in[4];
    const float* bih = (const float*)d_in[5];
    const float* bhh = (const float*)d_in[6];

    float* outs  = (float*)d_out;
    float* out_h = outs + (size_t)BS * TS * MS;
    float* out_c = out_h + (size_t)LAY * BS * MS;

    cudaFuncSetAttribute(rec_mma, cudaFuncAttributeMaxDynamicSharedMemorySize, REC_SMEM);
    cudaFuncSetAttribute(gemm_mma, cudaFuncAttributeMaxDynamicSharedMemorySize, GEMM_SMEM);

    conv_w_kernel<<<4096, 256>>>(Whh);
    conv_b_kernel<<<8192, 256>>>(Wih);
    for (int l = 0; l < LAY; l++) {
        conv_a_kernel<<<4096, 256>>>(x, l);
        gemm_mma<<<dim3(32, 64), 256, GEMM_SMEM>>>(
            l, bih + (size_t)l * JS, bhh + (size_t)l * JS);
        init_hf_kernel<<<(BS * MS + 255) / 256, 256>>>(h + (size_t)l * BS * MS);
        rec_mma<<<128, 512, REC_SMEM>>>(
            c + (size_t)l * BS * MS,
            out_c + (size_t)l * BS * MS,
            out_h + (size_t)l * BS * MS,
            outs, l);
    }
}